// round 16
// baseline (speedup 1.0000x reference)
#include <cuda_runtime.h>
#include <cuda_fp16.h>
#include <math.h>
#include <stdint.h>

// ---------------- problem constants ----------------
#define B_   4
#define N_   1024
#define D_   1024
#define H_   16
#define E_   12
#define KTOP 2
#define FF_  4
#define HD_  64
#define T_   (B_*N_)
#define A_   (T_*KTOP)
#define TD   ((long long)T_*D_)

// ---------------- static device scratch ----------------
__device__ __half g_xn_h [T_*D_];
__device__ float  g_psum [E_];
__device__ int    g_topi [T_*KTOP];
__device__ float  g_topw [T_*KTOP];
__device__ int    g_cnt  [E_];
__device__ int    g_off  [E_+1];
__device__ int    g_ctr  [E_];
__device__ int    g_done;
__device__ int    g_tok  [A_];
__device__ int    g_aidx [T_*KTOP];
__device__ __half g_projQKV[3LL*A_*D_];   // Q | K | V slots; O reuses slot 0
__device__ __half g_q_h  [T_*D_];
__device__ __half g_k_h  [T_*D_];
__device__ __half g_v_h  [T_*D_];
__device__ __half g_att_h[T_*D_];
__device__ float  g_h    [T_*D_];
__device__ __half g_hn_h [T_*D_];
__device__ __half g_ff1_h[T_*FF_*D_];
// half weight shadows
__device__ __half g_Wqkv_h[3LL*E_*D_*D_];
__device__ __half g_Wo_h  [(long long)E_*D_*D_];
__device__ __half g_W1_h  [(long long)FF_*D_*D_];
__device__ __half g_W2_h  [(long long)FF_*D_*D_];

// ---------------- PTX helpers ----------------
__device__ __forceinline__ uint32_t smem_u32(const void* p) {
    uint32_t a;
    asm("{ .reg .u64 t; cvta.to.shared.u64 t, %1; cvt.u32.u64 %0, t; }"
        : "=r"(a) : "l"(p));
    return a;
}
__device__ __forceinline__ void cp_async16s(uint32_t s, const void* g, int sz) {
    asm volatile("cp.async.cg.shared.global [%0], [%1], 16, %2;\n"
                 :: "r"(s), "l"(g), "r"(sz));
}
__device__ __forceinline__ void cp_commit() {
    asm volatile("cp.async.commit_group;\n");
}
template<int NN>
__device__ __forceinline__ void cp_wait() {
    asm volatile("cp.async.wait_group %0;\n" :: "n"(NN));
}
#define SWZ(o) ((o) ^ (((o) >> 3) & 0x70))

#define LDSM_X4(r0, r1, r2, r3, addr) \
    asm volatile("ldmatrix.sync.aligned.m8n8.x4.shared.b16 {%0,%1,%2,%3}, [%4];" \
        : "=r"(r0), "=r"(r1), "=r"(r2), "=r"(r3) : "r"(addr))
#define LDSM_X4_T(r0, r1, r2, r3, addr) \
    asm volatile("ldmatrix.sync.aligned.m8n8.x4.trans.shared.b16 {%0,%1,%2,%3}, [%4];" \
        : "=r"(r0), "=r"(r1), "=r"(r2), "=r"(r3) : "r"(addr))

__device__ __forceinline__ void mma_f16(float c[4],
        uint32_t a0, uint32_t a1, uint32_t a2, uint32_t a3,
        uint32_t b0, uint32_t b1) {
    asm volatile(
        "mma.sync.aligned.m16n8k16.row.col.f32.f16.f16.f32 "
        "{%0,%1,%2,%3}, {%4,%5,%6,%7}, {%8,%9}, {%0,%1,%2,%3};"
        : "+f"(c[0]), "+f"(c[1]), "+f"(c[2]), "+f"(c[3])
        : "r"(a0), "r"(a1), "r"(a2), "r"(a3), "r"(b0), "r"(b1));
}
__device__ __forceinline__ float fast_exp2(float x) {
    float y;
    asm("ex2.approx.f32 %0, %1;" : "=f"(y) : "f"(x));
    return y;
}
__device__ __forceinline__ uint32_t pack_h2(float a, float b) {
    __half2 h = __floats2half2_rn(a, b);
    uint32_t u;
    asm("mov.b32 %0, %1;" : "=r"(u) : "r"(*reinterpret_cast<uint32_t*>(&h)));
    return u;
}
__device__ __forceinline__ float gelu_tanh(float x) {
    float x3 = x * x * x;
    return 0.5f * x * (1.0f + tanhf(0.7978845608028654f * (x + 0.044715f * x3)));
}

// ======== fp16 HMMA GEMM: 128x256 CTA tile, 64x64 warp tile, 1 CTA/SM ========
#define GH_STAGES 3
#define GH_A_BYTES 16384
#define GH_STAGE_BYTES 49152          // A 16KB + B 32KB
#define GH_SMEM (GH_STAGES*GH_STAGE_BYTES)   // 147456

__global__ void __launch_bounds__(256, 1)
gemm_h(const __half* __restrict__ A, const __half* __restrict__ Bw,
       float* __restrict__ C, __half* __restrict__ Ch,
       int K, int lda, int ldb, int ldc,
       int zdiv, long long bz1, long long bz2, long long cz1,
       const int* __restrict__ seg_off, const int* __restrict__ tok,
       int Mfull, int epi,
       const float* __restrict__ bias, const float* __restrict__ resid) {
    extern __shared__ char smem[];
    uint32_t sb = smem_u32(smem);
    int tid = threadIdx.x, lane = tid & 31, warp = tid >> 5;
    int gid = lane >> 2, tig = lane & 3;
    int wm = warp & 1, wn = warp >> 1;   // 2 x 4 warps -> 64 x 64 per warp

    int z  = blockIdx.z;
    int z1 = z / zdiv;
    int z2 = z - z1 * zdiv;
    const __half* Bb = Bw + z1 * bz1 + z2 * bz2;
    float*  Cb  = C;
    __half* Chb = Ch ? Ch + z1 * cz1 : (__half*)0;

    int Mseg = Mfull;
    const int* grows = nullptr;
    if (seg_off) {
        int s = seg_off[z2];
        Mseg  = seg_off[z2 + 1] - s;
        grows = tok + s;
        if (Chb) Chb += (long long)s * ldc;
        if (Cb)  Cb  += (long long)s * ldc;
    }
    int m0 = blockIdx.y * 128;
    if (m0 >= Mseg) return;
    int n0 = blockIdx.x * 256;

    float acc[4][8][4];
    #pragma unroll
    for (int i = 0; i < 4; i++)
        #pragma unroll
        for (int j = 0; j < 8; j++)
            #pragma unroll
            for (int u = 0; u < 4; u++) acc[i][j][u] = 0.0f;

    int nk = K / 64;

    // ---- hoisted loader state ----
    uint32_t sdstA[4], aoff[4];
    int      apred[4];
    uint32_t sdstB[8], boff[8];
    {
        #pragma unroll
        for (int c = 0; c < 4; c++) {          // A: 1024 chunks
            int ch  = tid + 256 * c;
            int row = ch >> 3, kc = ch & 7;
            sdstA[c] = SWZ((uint32_t)(row * 128 + kc * 16));
            int gm = m0 + row;
            if (gm < Mseg) {
                int rr  = grows ? grows[gm] : gm;
                aoff[c] = (uint32_t)rr * (uint32_t)lda + (uint32_t)(kc * 8);
                apred[c] = 16;
            } else {
                aoff[c] = 0;
                apred[c] = 0;
            }
        }
        #pragma unroll
        for (int c = 0; c < 8; c++) {          // B: 2048 chunks (256 rows)
            int ch  = tid + 256 * c;
            int row = ch >> 3, kc = ch & 7;
            sdstB[c] = SWZ((uint32_t)(row * 128 + kc * 16));
            boff[c]  = (uint32_t)(n0 + row) * (uint32_t)ldb + (uint32_t)(kc * 8);
        }
    }
    uint32_t kbase = 0;

    auto issue = [&](int it) {
        uint32_t abase = sb + (uint32_t)((it % GH_STAGES) * GH_STAGE_BYTES);
        uint32_t bbase = abase + GH_A_BYTES;
        #pragma unroll
        for (int c = 0; c < 4; c++)
            cp_async16s(abase + sdstA[c], A + aoff[c] + kbase, apred[c]);
        #pragma unroll
        for (int c = 0; c < 8; c++)
            cp_async16s(bbase + sdstB[c], Bb + boff[c] + kbase, 16);
        cp_commit();
        kbase += 64;
    };

    // ---- hoisted per-warp ldmatrix offsets ----
    // SWZ(row*128 + ks*32 + hi) == SWZ(row*128 + hi) ^ (ks*32)  (XOR, bits 5-6)
    uint32_t a_lds[4], b_lds[4];
    {
        uint32_t hi = (uint32_t)((lane >> 4) * 16);
        #pragma unroll
        for (int i = 0; i < 4; i++) {
            int row = wm * 64 + i * 16 + (lane & 15);
            a_lds[i] = SWZ((uint32_t)(row * 128) + hi);
        }
        #pragma unroll
        for (int jp = 0; jp < 4; jp++) {
            int nrow = wn * 64 + jp * 16 + (lane & 15);
            b_lds[jp] = SWZ((uint32_t)(nrow * 128) + hi) + GH_A_BYTES;  // bit14, XOR-safe
        }
    }

    issue(0);
    if (nk > 1) issue(1);

    for (int it = 0; it < nk; it++) {
        if (it < nk - 1) cp_wait<1>(); else cp_wait<0>();
        __syncthreads();      // also orders prior-iter reads before issue overwrite
        if (it + 2 < nk) issue(it + 2);

        uint32_t abase = sb + (uint32_t)((it % GH_STAGES) * GH_STAGE_BYTES);

        #pragma unroll
        for (int ks = 0; ks < 4; ks++) {
            uint32_t ksx = (uint32_t)(ks * 32);
            uint32_t af[4][4];
            #pragma unroll
            for (int i = 0; i < 4; i++)
                LDSM_X4(af[i][0], af[i][1], af[i][2], af[i][3],
                        abase + (a_lds[i] ^ ksx));
            uint32_t bf[8][2];
            #pragma unroll
            for (int jp = 0; jp < 4; jp++) {
                uint32_t r0, r1, r2, r3;
                LDSM_X4(r0, r1, r2, r3, abase + (b_lds[jp] ^ ksx));
                bf[jp * 2][0] = r0; bf[jp * 2 + 1][0] = r1;
                bf[jp * 2][1] = r2; bf[jp * 2 + 1][1] = r3;
            }
            #pragma unroll
            for (int i = 0; i < 4; i++)
                #pragma unroll
                for (int j = 0; j < 8; j++)
                    mma_f16(acc[i][j], af[i][0], af[i][1], af[i][2], af[i][3],
                            bf[j][0], bf[j][1]);
        }
        // no trailing sync: next iteration's top sync provides WAR protection
    }

    #pragma unroll
    for (int i = 0; i < 4; i++)
        #pragma unroll
        for (int j = 0; j < 8; j++)
            #pragma unroll
            for (int h2 = 0; h2 < 2; h2++) {
                int r  = wm * 64 + i * 16 + gid + h2 * 8;
                int gm = m0 + r;
                if (gm >= Mseg) continue;
                int c  = wn * 64 + j * 8 + tig * 2;
                int gn = n0 + c;
                float v0 = acc[i][j][h2 * 2 + 0];
                float v1 = acc[i][j][h2 * 2 + 1];
                long long off = (long long)gm * ldc + gn;
                if (epi == 0) {
                    *reinterpret_cast<__half2*>(Chb + off) =
                        __floats2half2_rn(v0, v1);
                } else if (epi == 2) {
                    v0 = gelu_tanh(v0 + bias[gn]);
                    v1 = gelu_tanh(v1 + bias[gn + 1]);
                    *reinterpret_cast<__half2*>(Chb + off) =
                        __floats2half2_rn(v0, v1);
                } else {   // epi == 3
                    float2 rr = *reinterpret_cast<const float2*>(resid + off);
                    v0 = v0 + bias[gn] + rr.x;
                    v1 = v1 + bias[gn + 1] + rr.y;
                    *reinterpret_cast<float2*>(Cb + off) = make_float2(v0, v1);
                }
            }
}

// ================= fp16 flash attention (FA2 register P-reuse) =================
#define FAH_KS(buf) (8192 + (buf)*16384)
#define FAH_VS(buf) (16384 + (buf)*16384)
#define FAH_SMEM (40960*2)   // 81920 B

__global__ void __launch_bounds__(256)
flash_attn_h() {
    extern __shared__ __half smh[];
    uint32_t sb = smem_u32(smh);

    int bh = blockIdx.y;
    int b = bh >> 4, h = bh & 15;
    int q0 = blockIdx.x * 128;
    int tid = threadIdx.x, lane = tid & 31, w = tid >> 5;
    int gid = lane >> 2, tig = lane & 3;

    const __half* Qg = g_q_h + ((long long)(b * N_ + q0)) * D_ + h * HD_;

    auto issue_kv = [&](int t) {
        int buf = t & 1;
        const __half* Kg = g_k_h + ((long long)(b * N_ + t * 128)) * D_ + h * HD_;
        const __half* Vg = g_v_h + ((long long)(b * N_ + t * 128)) * D_ + h * HD_;
        uint32_t kb = sb + FAH_KS(buf) * 2;
        uint32_t vb = sb + FAH_VS(buf) * 2;
        #pragma unroll
        for (int p = 0; p < 4; p++) {
            int ch = tid + 256 * p;
            int r = ch >> 3, c16 = ch & 7;
            uint32_t doff = SWZ((uint32_t)(r * 128 + c16 * 16));
            cp_async16s(kb + doff, Kg + (long long)r * D_ + c16 * 8, 16);
            cp_async16s(vb + doff, Vg + (long long)r * D_ + c16 * 8, 16);
        }
        cp_commit();
    };

    {
        uint32_t qb = sb;
        #pragma unroll
        for (int p = 0; p < 4; p++) {
            int ch = tid + 256 * p;
            int r = ch >> 3, c16 = ch & 7;
            uint32_t doff = SWZ((uint32_t)(r * 128 + c16 * 16));
            cp_async16s(qb + doff, Qg + (long long)r * D_ + c16 * 8, 16);
        }
        cp_commit();
        issue_kv(0);
    }

    uint32_t qf[4][4];
    cp_wait<1>();
    __syncthreads();
    #pragma unroll
    for (int ks = 0; ks < 4; ks++) {
        int row = w * 16 + (lane & 15);
        uint32_t addr = sb + SWZ((uint32_t)(row * 128 + ks * 32 + (lane >> 4) * 16));
        LDSM_X4(qf[ks][0], qf[ks][1], qf[ks][2], qf[ks][3], addr);
    }

    float of[8][4];
    #pragma unroll
    for (int j = 0; j < 8; j++)
        #pragma unroll
        for (int u = 0; u < 4; u++) of[j][u] = 0.0f;
    float M0 = -1e30f, M1 = -1e30f, L0 = 0.f, L1 = 0.f;
    const float CE = 0.125f * 1.4426950408889634f;

    for (int t = 0; t < 8; t++) {
        __syncthreads();
        if (t < 7) issue_kv(t + 1);
        if (t < 7) cp_wait<1>(); else cp_wait<0>();
        __syncthreads();

        int buf = t & 1;
        uint32_t kb = sb + FAH_KS(buf) * 2;
        uint32_t vb = sb + FAH_VS(buf) * 2;

        float sf[16][4];
        #pragma unroll
        for (int j = 0; j < 16; j++)
            #pragma unroll
            for (int u = 0; u < 4; u++) sf[j][u] = 0.0f;
        #pragma unroll
        for (int ks = 0; ks < 4; ks++) {
            #pragma unroll
            for (int jj = 0; jj < 8; jj++) {
                int nrow = jj * 16 + (lane & 15);
                uint32_t addr = kb +
                    SWZ((uint32_t)(nrow * 128 + ks * 32 + (lane >> 4) * 16));
                uint32_t r0, r1, r2, r3;
                LDSM_X4(r0, r1, r2, r3, addr);
                mma_f16(sf[jj * 2],     qf[ks][0], qf[ks][1], qf[ks][2], qf[ks][3], r0, r2);
                mma_f16(sf[jj * 2 + 1], qf[ks][0], qf[ks][1], qf[ks][2], qf[ks][3], r1, r3);
            }
        }

        float mx0 = -1e30f, mx1 = -1e30f;
        #pragma unroll
        for (int j = 0; j < 16; j++) {
            mx0 = fmaxf(mx0, fmaxf(sf[j][0], sf[j][1]));
            mx1 = fmaxf(mx1, fmaxf(sf[j][2], sf[j][3]));
        }
        mx0 = fmaxf(mx0, __shfl_xor_sync(0xffffffffu, mx0, 1));
        mx0 = fmaxf(mx0, __shfl_xor_sync(0xffffffffu, mx0, 2));
        mx1 = fmaxf(mx1, __shfl_xor_sync(0xffffffffu, mx1, 1));
        mx1 = fmaxf(mx1, __shfl_xor_sync(0xffffffffu, mx1, 2));
        float nM0 = fmaxf(M0, mx0), nM1 = fmaxf(M1, mx1);
        float corr0 = fast_exp2(CE * (M0 - nM0));
        float corr1 = fast_exp2(CE * (M1 - nM1));

        uint32_t pa[8][4];
        float s0 = 0.f, s1 = 0.f;
        #pragma unroll
        for (int k2 = 0; k2 < 8; k2++) {
            float p00 = fast_exp2(CE * (sf[2*k2][0]   - nM0));
            float p01 = fast_exp2(CE * (sf[2*k2][1]   - nM0));
            float p02 = fast_exp2(CE * (sf[2*k2][2]   - nM1));
            float p03 = fast_exp2(CE * (sf[2*k2][3]   - nM1));
            float p10 = fast_exp2(CE * (sf[2*k2+1][0] - nM0));
            float p11 = fast_exp2(CE * (sf[2*k2+1][1] - nM0));
            float p12 = fast_exp2(CE * (sf[2*k2+1][2] - nM1));
            float p13 = fast_exp2(CE * (sf[2*k2+1][3] - nM1));
            s0 += p00 + p01 + p10 + p11;
            s1 += p02 + p03 + p12 + p13;
            pa[k2][0] = pack_h2(p00, p01);
            pa[k2][1] = pack_h2(p02, p03);
            pa[k2][2] = pack_h2(p10, p11);
            pa[k2][3] = pack_h2(p12, p13);
        }
        s0 += __shfl_xor_sync(0xffffffffu, s0, 1);
        s0 += __shfl_xor_sync(0xffffffffu, s0, 2);
        s1 += __shfl_xor_sync(0xffffffffu, s1, 1);
        s1 += __shfl_xor_sync(0xffffffffu, s1, 2);
        L0 = L0 * corr0 + s0;
        L1 = L1 * corr1 + s1;
        M0 = nM0; M1 = nM1;

        #pragma unroll
        for (int j = 0; j < 8; j++) {
            of[j][0] *= corr0; of[j][1] *= corr0;
            of[j][2] *= corr1; of[j][3] *= corr1;
        }

        #pragma unroll
        for (int k2 = 0; k2 < 8; k2++) {
            #pragma unroll
            for (int jp = 0; jp < 4; jp++) {
                int vrow = k2 * 16 + (lane & 15);
                uint32_t vaddr = vb +
                    SWZ((uint32_t)(vrow * 128 + jp * 32 + (lane >> 4) * 16));
                uint32_t r0, r1, r2, r3;
                LDSM_X4_T(r0, r1, r2, r3, vaddr);
                mma_f16(of[jp * 2],     pa[k2][0], pa[k2][1], pa[k2][2], pa[k2][3], r0, r1);
                mma_f16(of[jp * 2 + 1], pa[k2][0], pa[k2][1], pa[k2][2], pa[k2][3], r2, r3);
            }
        }
    }

    float i0 = 1.0f / L0, i1 = 1.0f / L1;
    __half* Og = g_att_h + ((long long)(b * N_ + q0 + w * 16)) * D_ + h * HD_;
    #pragma unroll
    for (int j = 0; j < 8; j++) {
        *reinterpret_cast<__half2*>(&Og[(long long)gid * D_ + j * 8 + tig * 2]) =
            __floats2half2_rn(of[j][0] * i0, of[j][1] * i0);
        *reinterpret_cast<__half2*>(&Og[(long long)(gid + 8) * D_ + j * 8 + tig * 2]) =
            __floats2half2_rn(of[j][2] * i1, of[j][3] * i1);
    }
}

// ---------------- small kernels ----------------
__global__ void f2h_all_kernel(const float* s0, const float* s1, const float* s2,
                               const float* s3, const float* s4, const float* s5,
                               __half* d0, __half* d1, __half* d2,
                               __half* d3, __half* d4, __half* d5,
                               long long c1, long long c2, long long c3,
                               long long c4, long long c5, long long c6) {
    long long i = (long long)blockIdx.x * blockDim.x + threadIdx.x;
    if (blockIdx.x == 0) {
        if (threadIdx.x < E_) {
            g_cnt[threadIdx.x]  = 0;
            g_psum[threadIdx.x] = 0.0f;
            g_ctr[threadIdx.x]  = 0;
        }
        if (threadIdx.x == E_) g_done = 0;
    }
    if (i >= c6) return;
    const float* s; __half* d; long long base;
    if      (i < c1) { s = s0; d = d0; base = 0;  }
    else if (i < c2) { s = s1; d = d1; base = c1; }
    else if (i < c3) { s = s2; d = d2; base = c2; }
    else if (i < c4) { s = s3; d = d3; base = c3; }
    else if (i < c5) { s = s4; d = d4; base = c4; }
    else             { s = s5; d = d5; base = c5; }
    long long j = i - base;
    const float4* s4p = reinterpret_cast<const float4*>(s);
    float4 a = s4p[j * 2], bb = s4p[j * 2 + 1];
    union { __half2 h[4]; uint4 u; } pack;
    pack.h[0] = __floats2half2_rn(a.x, a.y);
    pack.h[1] = __floats2half2_rn(a.z, a.w);
    pack.h[2] = __floats2half2_rn(bb.x, bb.y);
    pack.h[3] = __floats2half2_rn(bb.z, bb.w);
    reinterpret_cast<uint4*>(d)[j] = pack.u;
}

// Router: warp per token. Inline LN + xn_h store, logits, softmax, top-2,
// counts + psum atomics. Last block finalizes scan + lb (ticket).
__global__ void router_kernel(const float* __restrict__ x, const float* __restrict__ Wr,
                              const float* __restrict__ g, const float* __restrict__ bb,
                              float* __restrict__ out, int out_size) {
    int warp = (blockIdx.x * blockDim.x + threadIdx.x) >> 5;
    int lane = threadIdx.x & 31;
    if (warp < T_) {
        const float* xr = x + (long long)warp * D_;
        float xv[32];
        float s = 0.f;
        #pragma unroll
        for (int ii = 0; ii < 32; ii++) { xv[ii] = xr[lane + 32 * ii]; s += xv[ii]; }
        #pragma unroll
        for (int o = 16; o; o >>= 1) s += __shfl_xor_sync(0xffffffffu, s, o);
        float m = s * (1.0f / D_);
        float q = 0.f;
        #pragma unroll
        for (int ii = 0; ii < 32; ii++) { float d = xv[ii] - m; q += d * d; }
        #pragma unroll
        for (int o = 16; o; o >>= 1) q += __shfl_xor_sync(0xffffffffu, q, o);
        float rstd = rsqrtf(q * (1.0f / D_) + 1e-5f);

        float acc[E_];
        #pragma unroll
        for (int e = 0; e < E_; e++) acc[e] = 0.f;
        #pragma unroll
        for (int ii = 0; ii < 32; ii++) {
            int i = lane + 32 * ii;
            float xn = (xv[ii] - m) * rstd * g[i] + bb[i];
            g_xn_h[(long long)warp * D_ + i] = __float2half(xn);
            #pragma unroll
            for (int e = 0; e < E_; e++) acc[e] += xn * Wr[e * D_ + i];
        }
        #pragma unroll
        for (int e = 0; e < E_; e++)
            #pragma unroll
            for (int o = 16; o; o >>= 1) acc[e] += __shfl_xor_sync(0xffffffffu, acc[e], o);
        if (lane == 0) {
            float mx = acc[0];
            #pragma unroll
            for (int e = 1; e < E_; e++) mx = fmaxf(mx, acc[e]);
            float p[E_], ss = 0.f;
            #pragma unroll
            for (int e = 0; e < E_; e++) { p[e] = expf(acc[e] - mx); ss += p[e]; }
            float inv = 1.0f / ss;
            #pragma unroll
            for (int e = 0; e < E_; e++) {
                p[e] *= inv;
                atomicAdd(&g_psum[e], p[e]);
            }
            int i0 = 0;
            #pragma unroll
            for (int e = 1; e < E_; e++) if (p[e] > p[i0]) i0 = e;
            int i1 = (i0 == 0) ? 1 : 0;
            #pragma unroll
            for (int e = 0; e < E_; e++) if (e != i0 && p[e] > p[i1]) i1 = e;
            float v0 = p[i0], v1 = p[i1];
            float wsum = v0 + v1 + 1e-6f;
            g_topi[warp * 2 + 0] = i0;
            g_topi[warp * 2 + 1] = i1;
            g_topw[warp * 2 + 0] = v0 / wsum;
            g_topw[warp * 2 + 1] = v1 / wsum;
            atomicAdd(&g_cnt[i0], 1);
            atomicAdd(&g_cnt[i1], 1);
        }
    }
    __syncthreads();
    if (threadIdx.x == 0) {
        __threadfence();
        int t = atomicAdd(&g_done, 1);
        if (t == (int)gridDim.x - 1) {
            int cnt[E_];
            float ps[E_];
            #pragma unroll
            for (int e = 0; e < E_; e++) {
                cnt[e] = atomicAdd(&g_cnt[e], 0);
                ps[e]  = atomicAdd(&g_psum[e], 0.0f);
            }
            int s = 0;
            #pragma unroll
            for (int e = 0; e < E_; e++) { g_off[e] = s; s += cnt[e]; }
            g_off[E_] = s;
            float lb = 0.f;
            float denom = (float)A_ + 1e-6f;
            #pragma unroll
            for (int e = 0; e < E_; e++)
                lb += ((float)cnt[e] / denom) * ps[e];
            lb *= (float)E_;
            if (out_size > (int)TD) out[TD] = lb;
        }
    }
}

// grid-parallel scatter (global atomics on 12 counters)
__global__ void scatter_kernel() {
    int idx = blockIdx.x * blockDim.x + threadIdx.x;
    if (idx >= A_) return;
    int e = g_topi[idx];
    int pos = g_off[e] + atomicAdd(&g_ctr[e], 1);
    g_tok[pos]  = idx >> 1;
    g_aidx[idx] = pos;
}

// combine Q,K,V (half proj -> half q/k/v)
__global__ void combine_qkv_kernel() {
    long long t = blockIdx.x;
    int tid = threadIdx.x;
    int a0 = g_aidx[t * 2 + 0], a1 = g_aidx[t * 2 + 1];
    float w0 = g_topw[t * 2 + 0], w1 = g_topw[t * 2 + 1];
    const __half2* pQ = reinterpret_cast<const __half2*>(g_projQKV);
    const __half2* pK = reinterpret_cast<const __half2*>(g_projQKV + (long long)A_ * D_);
    const __half2* pV = reinterpret_cast<const __half2*>(g_projQKV + 2LL * A_ * D_);
    long long r0 = (long long)a0 * (D_ / 2), r1 = (long long)a1 * (D_ / 2);
    long long tb = t * (D_ / 2);
    #pragma unroll
    for (int i = 0; i < 2; i++) {
        int c = tid + 256 * i;
        float2 q0 = __half22float2(pQ[r0 + c]), q1 = __half22float2(pQ[r1 + c]);
        float2 k0 = __half22float2(pK[r0 + c]), k1 = __half22float2(pK[r1 + c]);
        float2 v0 = __half22float2(pV[r0 + c]), v1 = __half22float2(pV[r1 + c]);
        reinterpret_cast<__half2*>(g_q_h)[tb + c] =
            __floats2half2_rn(w0 * q0.x + w1 * q1.x, w0 * q0.y + w1 * q1.y);
        reinterpret_cast<__half2*>(g_k_h)[tb + c] =
            __floats2half2_rn(w0 * k0.x + w1 * k1.x, w0 * k0.y + w1 * k1.y);
        reinterpret_cast<__half2*>(g_v_h)[tb + c] =
            __floats2half2_rn(w0 * v0.x + w1 * v1.x, w0 * v0.y + w1 * v1.y);
    }
}

// LN2 fused with combine_o
__global__ void ln2_fused_kernel(const float* __restrict__ x,
                                 const float* __restrict__ g, const float* __restrict__ b) {
    __shared__ float sh[33];
    long long row = blockIdx.x;
    int tid = threadIdx.x;
    int a0 = g_aidx[row * 2 + 0], a1 = g_aidx[row * 2 + 1];
    float w0 = g_topw[row * 2 + 0], w1 = g_topw[row * 2 + 1];
    const __half* pO = g_projQKV;
    long long r0 = (long long)a0 * D_, r1 = (long long)a1 * D_;
    float v[4];
    #pragma unroll
    for (int i = 0; i < 4; i++) {
        int c = tid + 256 * i;
        float o = w0 * __half2float(pO[r0 + c]) + w1 * __half2float(pO[r1 + c]);
        v[i] = x[row * D_ + c] + o;
        g_h[row * D_ + c] = v[i];
    }
    float s = v[0] + v[1] + v[2] + v[3];
    #pragma unroll
    for (int o = 16; o; o >>= 1) s += __shfl_xor_sync(0xffffffffu, s, o);
    if ((tid & 31) == 0) sh[tid >> 5] = s;
    __syncthreads();
    if (tid < 32) {
        s = (tid < 8) ? sh[tid] : 0.0f;
        #pragma unroll
        for (int o = 16; o; o >>= 1) s += __shfl_xor_sync(0xffffffffu, s, o);
        if (tid == 0) sh[0] = s;
    }
    __syncthreads();
    float m = sh[0] * (1.0f / D_);
    __syncthreads();
    float q = 0.f;
    #pragma unroll
    for (int i = 0; i < 4; i++) { float d = v[i] - m; q += d * d; }
    #pragma unroll
    for (int o = 16; o; o >>= 1) q += __shfl_xor_sync(0xffffffffu, q, o);
    if ((tid & 31) == 0) sh[tid >> 5] = q;
    __syncthreads();
    if (tid < 32) {
        q = (tid < 8) ? sh[tid] : 0.0f;
        #pragma unroll
        for (int o = 16; o; o >>= 1) q += __shfl_xor_sync(0xffffffffu, q, o);
        if (tid == 0) sh[0] = q;
    }
    __syncthreads();
    float rstd = rsqrtf(sh[0] * (1.0f / D_) + 1e-5f);
    #pragma unroll
    for (int i = 0; i < 4; i++) {
        int c = tid + 256 * i;
        g_hn_h[row * D_ + c] = __float2half((v[i] - m) * rstd * g[c] + b[c]);
    }
}

// ---------------- host launch ----------------
extern "C" void kernel_launch(void* const* d_in, const int* in_sizes, int n_in,
                              void* d_out, int out_size) {
    const float* x   = (const float*)d_in[0];
    const float* Wr  = (const float*)d_in[1];
    const float* Wq  = (const float*)d_in[2];
    const float* Wk  = (const float*)d_in[3];
    const float* Wv  = (const float*)d_in[4];
    const float* Wo  = (const float*)d_in[5];
    const float* W1  = (const float*)d_in[6];
    const float* b1  = (const float*)d_in[7];
    const float* W2  = (const float*)d_in[8];
    const float* b2  = (const float*)d_in[9];
    const float* g1  = (const float*)d_in[10];
    const float* be1 = (const float*)d_in[11];
    const float* g2  = (const float*)d_in[12];
    const float* be2 = (const float*)d_in[13];
    float* out = (float*)d_out;

    float  *p_h;
    __half *p_xn_h, *p_att_h, *p_hn_h, *p_ff1_h, *p_projQKV;
    __half *p_Wqkv_h, *p_Wo_h, *p_W1_h, *p_W2_h;
    int *p_off, *p_tok;
    cudaGetSymbolAddress((void**)&p_xn_h,   g_xn_h);
    cudaGetSymbolAddress((void**)&p_projQKV,g_projQKV);
    cudaGetSymbolAddress((void**)&p_att_h,  g_att_h);
    cudaGetSymbolAddress((void**)&p_h,      g_h);
    cudaGetSymbolAddress((void**)&p_hn_h,   g_hn_h);
    cudaGetSymbolAddress((void**)&p_ff1_h,  g_ff1_h);
    cudaGetSymbolAddress((void**)&p_Wqkv_h, g_Wqkv_h);
    cudaGetSymbolAddress((void**)&p_Wo_h,   g_Wo_h);
    cudaGetSymbolAddress((void**)&p_W1_h,   g_W1_h);
    cudaGetSymbolAddress((void**)&p_W2_h,   g_W2_h);
    cudaGetSymbolAddress((void**)&p_off,    g_off);
    cudaGetSymbolAddress((void**)&p_tok,    g_tok);

    const long long EDD  = (long long)E_ * D_ * D_;
    const long long FFDD = (long long)FF_ * D_ * D_;
    const long long DD   = (long long)D_ * D_;
    cudaFuncSetAttribute(gemm_h,
                         cudaFuncAttributeMaxDynamicSharedMemorySize, GH_SMEM);
    cudaFuncSetAttribute(flash_attn_h,
                         cudaFuncAttributeMaxDynamicSharedMemorySize, FAH_SMEM);

    // fused weight conversion + counter init
    {
        long long n8e = EDD / 8, n8f = FFDD / 8;
        long long c1 = n8e, c2 = 2*n8e, c3 = 3*n8e, c4 = 4*n8e,
                  c5 = 4*n8e + n8f, c6 = 4*n8e + 2*n8f;
        int blocks = (int)((c6 + 255) / 256);
        f2h_all_kernel<<<blocks, 256>>>(Wq, Wk, Wv, Wo, W1, W2,
            p_Wqkv_h, p_Wqkv_h + EDD, p_Wqkv_h + 2*EDD, p_Wo_h, p_W1_h, p_W2_h,
            c1, c2, c3, c4, c5, c6);
    }

    router_kernel<<<T_ / 8, 256>>>(x, Wr, g1, be1, out, out_size);
    scatter_kernel<<<A_ / 256, 256>>>();

    // merged grouped QKV GEMM: z = p*E + e  (y=12: max expert load 1536 rows)
    gemm_h<<<dim3(D_ / 256, 12, 3 * E_), 256, GH_SMEM>>>(
        p_xn_h, p_Wqkv_h, nullptr, p_projQKV,
        D_, D_, D_, D_, E_, EDD, DD, (long long)A_ * D_,
        p_off, p_tok, A_, 0, nullptr, nullptr);
    combine_qkv_kernel<<<T_, 256>>>();

    flash_attn_h<<<dim3(N_ / 128, B_ * H_), 256, FAH_SMEM>>>();

    // grouped O projection (into proj slot 0); combine fused into LN2
    gemm_h<<<dim3(D_ / 256, 12, E_), 256, GH_SMEM>>>(
        p_att_h, p_Wo_h, nullptr, p_projQKV,
        D_, D_, D_, D_, E_, 0, DD, 0,
        p_off, p_tok, A_, 0, nullptr, nullptr);

    ln2_fused_kernel<<<T_, 256>>>(x, g2, be2);

    // FFN1
    gemm_h<<<dim3(FF_ * D_ / 256, T_ / 128, 1), 256, GH_SMEM>>>(
        p_hn_h, p_W1_h, nullptr, p_ff1_h,
        D_, D_, D_, FF_ * D_, 1, 0, 0, 0,
        nullptr, nullptr, T_, 2, b1, nullptr);

    // FFN2 -> d_out
    gemm_h<<<dim3(D_ / 256, T_ / 128, 1), 256, GH_SMEM>>>(
        p_ff1_h, p_W2_h, out, nullptr,
        FF_ * D_, FF_ * D_, FF_ * D_, D_, 1, 0, 0, 0,
        nullptr, nullptr, T_, 3, b2, p_h);
}

// round 17
// speedup vs baseline: 1.0338x; 1.0338x over previous
#include <cuda_runtime.h>
#include <cuda_fp16.h>
#include <math.h>
#include <stdint.h>

// ---------------- problem constants ----------------
#define B_   4
#define N_   1024
#define D_   1024
#define H_   16
#define E_   12
#define KTOP 2
#define FF_  4
#define HD_  64
#define T_   (B_*N_)
#define A_   (T_*KTOP)
#define TD   ((long long)T_*D_)

// ---------------- static device scratch ----------------
__device__ __half g_xn_h [T_*D_];
__device__ float  g_psum [E_];
__device__ int    g_topi [T_*KTOP];
__device__ float  g_topw [T_*KTOP];
__device__ int    g_cnt  [E_];
__device__ int    g_off  [E_+1];
__device__ int    g_ctr  [E_];
__device__ int    g_done;
__device__ int    g_tok  [A_];
__device__ int    g_aidx [T_*KTOP];
__device__ __half g_projQKV[3LL*A_*D_];   // Q | K | V slots; O reuses slot 0
__device__ __half g_q_h  [T_*D_];
__device__ __half g_k_h  [T_*D_];
__device__ __half g_v_h  [T_*D_];
__device__ __half g_att_h[T_*D_];
__device__ float  g_h    [T_*D_];
__device__ __half g_hn_h [T_*D_];
__device__ __half g_ff1_h[T_*FF_*D_];
// half weight shadows
__device__ __half g_Wqkv_h[3LL*E_*D_*D_];
__device__ __half g_Wo_h  [(long long)E_*D_*D_];
__device__ __half g_W1_h  [(long long)FF_*D_*D_];
__device__ __half g_W2_h  [(long long)FF_*D_*D_];

// ---------------- PTX helpers ----------------
__device__ __forceinline__ uint32_t smem_u32(const void* p) {
    uint32_t a;
    asm("{ .reg .u64 t; cvta.to.shared.u64 t, %1; cvt.u32.u64 %0, t; }"
        : "=r"(a) : "l"(p));
    return a;
}
__device__ __forceinline__ void cp_async16s(uint32_t s, const void* g, int sz) {
    asm volatile("cp.async.cg.shared.global [%0], [%1], 16, %2;\n"
                 :: "r"(s), "l"(g), "r"(sz));
}
__device__ __forceinline__ void cp_commit() {
    asm volatile("cp.async.commit_group;\n");
}
template<int NN>
__device__ __forceinline__ void cp_wait() {
    asm volatile("cp.async.wait_group %0;\n" :: "n"(NN));
}
#define SWZ(o) ((o) ^ (((o) >> 3) & 0x70))

#define LDSM_X4(r0, r1, r2, r3, addr) \
    asm volatile("ldmatrix.sync.aligned.m8n8.x4.shared.b16 {%0,%1,%2,%3}, [%4];" \
        : "=r"(r0), "=r"(r1), "=r"(r2), "=r"(r3) : "r"(addr))
#define LDSM_X4_T(r0, r1, r2, r3, addr) \
    asm volatile("ldmatrix.sync.aligned.m8n8.x4.trans.shared.b16 {%0,%1,%2,%3}, [%4];" \
        : "=r"(r0), "=r"(r1), "=r"(r2), "=r"(r3) : "r"(addr))

__device__ __forceinline__ void mma_f16(float c[4],
        uint32_t a0, uint32_t a1, uint32_t a2, uint32_t a3,
        uint32_t b0, uint32_t b1) {
    asm volatile(
        "mma.sync.aligned.m16n8k16.row.col.f32.f16.f16.f32 "
        "{%0,%1,%2,%3}, {%4,%5,%6,%7}, {%8,%9}, {%0,%1,%2,%3};"
        : "+f"(c[0]), "+f"(c[1]), "+f"(c[2]), "+f"(c[3])
        : "r"(a0), "r"(a1), "r"(a2), "r"(a3), "r"(b0), "r"(b1));
}
__device__ __forceinline__ float fast_exp2(float x) {
    float y;
    asm("ex2.approx.f32 %0, %1;" : "=f"(y) : "f"(x));
    return y;
}
__device__ __forceinline__ uint32_t pack_h2(float a, float b) {
    __half2 h = __floats2half2_rn(a, b);
    uint32_t u;
    asm("mov.b32 %0, %1;" : "=r"(u) : "r"(*reinterpret_cast<uint32_t*>(&h)));
    return u;
}
__device__ __forceinline__ float gelu_tanh(float x) {
    float x3 = x * x * x;
    return 0.5f * x * (1.0f + tanhf(0.7978845608028654f * (x + 0.044715f * x3)));
}

// ===== fp16 HMMA GEMM: 128x128 tile, 2 CTAs/SM, hoisted addresses (R15 best) =====
#define GH_STAGES 3
#define GH_STAGE_BYTES 32768
#define GH_SMEM (GH_STAGES*GH_STAGE_BYTES)

__global__ void __launch_bounds__(256, 2)
gemm_h(const __half* __restrict__ A, const __half* __restrict__ Bw,
       float* __restrict__ C, __half* __restrict__ Ch,
       int K, int lda, int ldb, int ldc,
       int zdiv, long long bz1, long long bz2, long long cz1,
       const int* __restrict__ seg_off, const int* __restrict__ tok,
       int Mfull, int epi,
       const float* __restrict__ bias, const float* __restrict__ resid) {
    extern __shared__ char smem[];
    uint32_t sb = smem_u32(smem);
    int tid = threadIdx.x, lane = tid & 31, warp = tid >> 5;
    int gid = lane >> 2, tig = lane & 3;
    int wm = warp & 1, wn = warp >> 1;

    int z  = blockIdx.z;
    int z1 = z / zdiv;
    int z2 = z - z1 * zdiv;
    const __half* Bb = Bw + z1 * bz1 + z2 * bz2;
    float*  Cb  = C;
    __half* Chb = Ch ? Ch + z1 * cz1 : (__half*)0;

    int Mseg = Mfull;
    const int* grows = nullptr;
    if (seg_off) {
        int s = seg_off[z2];
        Mseg  = seg_off[z2 + 1] - s;
        grows = tok + s;
        if (Chb) Chb += (long long)s * ldc;
        if (Cb)  Cb  += (long long)s * ldc;
    }
    int m0 = blockIdx.y * 128;
    if (m0 >= Mseg) return;
    int n0 = blockIdx.x * 128;

    float acc[4][4][4];
    #pragma unroll
    for (int i = 0; i < 4; i++)
        #pragma unroll
        for (int j = 0; j < 4; j++)
            #pragma unroll
            for (int u = 0; u < 4; u++) acc[i][j][u] = 0.0f;

    int nk = K / 64;

    // ---- hoisted loader state ----
    uint32_t sdst[4], aoff[4], boff[4];
    int      apred[4];
    {
        #pragma unroll
        for (int c = 0; c < 4; c++) {
            int ch  = tid + 256 * c;
            int row = ch >> 3, kc = ch & 7;
            sdst[c] = SWZ((uint32_t)(row * 128 + kc * 16));
            int gm = m0 + row;
            if (gm < Mseg) {
                int rr  = grows ? grows[gm] : gm;
                aoff[c] = (uint32_t)rr * (uint32_t)lda + (uint32_t)(kc * 8);
                apred[c] = 16;
            } else {
                aoff[c] = 0;
                apred[c] = 0;
            }
            boff[c] = (uint32_t)(n0 + row) * (uint32_t)ldb + (uint32_t)(kc * 8);
        }
    }
    uint32_t kbase = 0;

    auto issue = [&](int it) {
        uint32_t abase = sb + (uint32_t)((it % GH_STAGES) * GH_STAGE_BYTES);
        uint32_t bbase = abase + 16384;
        #pragma unroll
        for (int c = 0; c < 4; c++)
            cp_async16s(abase + sdst[c], A + aoff[c] + kbase, apred[c]);
        #pragma unroll
        for (int c = 0; c < 4; c++)
            cp_async16s(bbase + sdst[c], Bb + boff[c] + kbase, 16);
        cp_commit();
        kbase += 64;
    };

    // ---- hoisted per-warp ldmatrix offsets (XOR identity, bits 5-6) ----
    uint32_t a_lds[4], b_lds[2];
    {
        uint32_t hi = (uint32_t)((lane >> 4) * 16);
        #pragma unroll
        for (int i = 0; i < 4; i++) {
            int row = wm * 64 + i * 16 + (lane & 15);
            a_lds[i] = SWZ((uint32_t)(row * 128) + hi);
        }
        #pragma unroll
        for (int jp = 0; jp < 2; jp++) {
            int nrow = wn * 32 + jp * 16 + (lane & 15);
            b_lds[jp] = SWZ((uint32_t)(nrow * 128) + hi) + 16384;
        }
    }

    issue(0);
    if (nk > 1) issue(1);

    for (int it = 0; it < nk; it++) {
        if (it < nk - 1) cp_wait<1>(); else cp_wait<0>();
        __syncthreads();
        if (it + 2 < nk) issue(it + 2);

        uint32_t abase = sb + (uint32_t)((it % GH_STAGES) * GH_STAGE_BYTES);

        #pragma unroll
        for (int ks = 0; ks < 4; ks++) {
            uint32_t ksx = (uint32_t)(ks * 32);
            uint32_t af[4][4];
            #pragma unroll
            for (int i = 0; i < 4; i++)
                LDSM_X4(af[i][0], af[i][1], af[i][2], af[i][3],
                        abase + (a_lds[i] ^ ksx));
            uint32_t bf[4][2];
            #pragma unroll
            for (int jp = 0; jp < 2; jp++) {
                uint32_t r0, r1, r2, r3;
                LDSM_X4(r0, r1, r2, r3, abase + (b_lds[jp] ^ ksx));
                bf[jp * 2][0] = r0; bf[jp * 2 + 1][0] = r1;
                bf[jp * 2][1] = r2; bf[jp * 2 + 1][1] = r3;
            }
            #pragma unroll
            for (int i = 0; i < 4; i++)
                #pragma unroll
                for (int j = 0; j < 4; j++)
                    mma_f16(acc[i][j], af[i][0], af[i][1], af[i][2], af[i][3],
                            bf[j][0], bf[j][1]);
        }
        __syncthreads();
    }

    #pragma unroll
    for (int i = 0; i < 4; i++)
        #pragma unroll
        for (int j = 0; j < 4; j++)
            #pragma unroll
            for (int h2 = 0; h2 < 2; h2++) {
                int r  = wm * 64 + i * 16 + gid + h2 * 8;
                int gm = m0 + r;
                if (gm >= Mseg) continue;
                int c  = wn * 32 + j * 8 + tig * 2;
                int gn = n0 + c;
                float v0 = acc[i][j][h2 * 2 + 0];
                float v1 = acc[i][j][h2 * 2 + 1];
                long long off = (long long)gm * ldc + gn;
                if (epi == 0) {
                    *reinterpret_cast<__half2*>(Chb + off) =
                        __floats2half2_rn(v0, v1);
                } else if (epi == 2) {
                    v0 = gelu_tanh(v0 + bias[gn]);
                    v1 = gelu_tanh(v1 + bias[gn + 1]);
                    *reinterpret_cast<__half2*>(Chb + off) =
                        __floats2half2_rn(v0, v1);
                } else {   // epi == 3
                    float2 rr = *reinterpret_cast<const float2*>(resid + off);
                    v0 = v0 + bias[gn] + rr.x;
                    v1 = v1 + bias[gn + 1] + rr.y;
                    *reinterpret_cast<float2*>(Cb + off) = make_float2(v0, v1);
                }
            }
}

// ======= fp16 flash attention (FA2 register P-reuse, hoisted addresses) =======
#define FAH_KS(buf) (8192 + (buf)*16384)
#define FAH_VS(buf) (16384 + (buf)*16384)
#define FAH_SMEM (40960*2)   // 81920 B

__global__ void __launch_bounds__(256)
flash_attn_h() {
    extern __shared__ __half smh[];
    uint32_t sb = smem_u32(smh);

    int bh = blockIdx.y;
    int b = bh >> 4, h = bh & 15;
    int q0 = blockIdx.x * 128;
    int tid = threadIdx.x, lane = tid & 31, w = tid >> 5;
    int gid = lane >> 2, tig = lane & 3;

    const __half* Qg = g_q_h + ((long long)(b * N_ + q0)) * D_ + h * HD_;

    auto issue_kv = [&](int t) {
        int buf = t & 1;
        const __half* Kg = g_k_h + ((long long)(b * N_ + t * 128)) * D_ + h * HD_;
        const __half* Vg = g_v_h + ((long long)(b * N_ + t * 128)) * D_ + h * HD_;
        uint32_t kb = sb + FAH_KS(buf) * 2;
        uint32_t vb = sb + FAH_VS(buf) * 2;
        #pragma unroll
        for (int p = 0; p < 4; p++) {
            int ch = tid + 256 * p;
            int r = ch >> 3, c16 = ch & 7;
            uint32_t doff = SWZ((uint32_t)(r * 128 + c16 * 16));
            cp_async16s(kb + doff, Kg + (long long)r * D_ + c16 * 8, 16);
            cp_async16s(vb + doff, Vg + (long long)r * D_ + c16 * 8, 16);
        }
        cp_commit();
    };

    {
        uint32_t qb = sb;
        #pragma unroll
        for (int p = 0; p < 4; p++) {
            int ch = tid + 256 * p;
            int r = ch >> 3, c16 = ch & 7;
            uint32_t doff = SWZ((uint32_t)(r * 128 + c16 * 16));
            cp_async16s(qb + doff, Qg + (long long)r * D_ + c16 * 8, 16);
        }
        cp_commit();
        issue_kv(0);
    }

    // hoisted ldmatrix row offsets (XOR identity: col bits 5-6 disjoint from
    // swizzle source bits 7-9; hi = bit 4)
    uint32_t row_lds[8];   // rows jj*16 + (lane&15), jj = 0..7 (used for K, V, Q)
    {
        uint32_t hi = (uint32_t)((lane >> 4) * 16);
        #pragma unroll
        for (int jj = 0; jj < 8; jj++) {
            int nrow = jj * 16 + (lane & 15);
            row_lds[jj] = SWZ((uint32_t)(nrow * 128) + hi);
        }
    }

    uint32_t qf[4][4];
    cp_wait<1>();
    __syncthreads();
    #pragma unroll
    for (int ks = 0; ks < 4; ks++) {
        uint32_t addr = sb + (row_lds[w] ^ (uint32_t)(ks * 32));
        LDSM_X4(qf[ks][0], qf[ks][1], qf[ks][2], qf[ks][3], addr);
    }

    float of[8][4];
    #pragma unroll
    for (int j = 0; j < 8; j++)
        #pragma unroll
        for (int u = 0; u < 4; u++) of[j][u] = 0.0f;
    float M0 = -1e30f, M1 = -1e30f, L0 = 0.f, L1 = 0.f;
    const float CE = 0.125f * 1.4426950408889634f;

    for (int t = 0; t < 8; t++) {
        __syncthreads();
        if (t < 7) issue_kv(t + 1);
        if (t < 7) cp_wait<1>(); else cp_wait<0>();
        __syncthreads();

        int buf = t & 1;
        uint32_t kb = sb + FAH_KS(buf) * 2;
        uint32_t vb = sb + FAH_VS(buf) * 2;

        float sf[16][4];
        #pragma unroll
        for (int j = 0; j < 16; j++)
            #pragma unroll
            for (int u = 0; u < 4; u++) sf[j][u] = 0.0f;
        #pragma unroll
        for (int ks = 0; ks < 4; ks++) {
            uint32_t ksx = (uint32_t)(ks * 32);
            #pragma unroll
            for (int jj = 0; jj < 8; jj++) {
                uint32_t r0, r1, r2, r3;
                LDSM_X4(r0, r1, r2, r3, kb + (row_lds[jj] ^ ksx));
                mma_f16(sf[jj * 2],     qf[ks][0], qf[ks][1], qf[ks][2], qf[ks][3], r0, r2);
                mma_f16(sf[jj * 2 + 1], qf[ks][0], qf[ks][1], qf[ks][2], qf[ks][3], r1, r3);
            }
        }

        float mx0 = -1e30f, mx1 = -1e30f;
        #pragma unroll
        for (int j = 0; j < 16; j++) {
            mx0 = fmaxf(mx0, fmaxf(sf[j][0], sf[j][1]));
            mx1 = fmaxf(mx1, fmaxf(sf[j][2], sf[j][3]));
        }
        mx0 = fmaxf(mx0, __shfl_xor_sync(0xffffffffu, mx0, 1));
        mx0 = fmaxf(mx0, __shfl_xor_sync(0xffffffffu, mx0, 2));
        mx1 = fmaxf(mx1, __shfl_xor_sync(0xffffffffu, mx1, 1));
        mx1 = fmaxf(mx1, __shfl_xor_sync(0xffffffffu, mx1, 2));
        float nM0 = fmaxf(M0, mx0), nM1 = fmaxf(M1, mx1);
        float corr0 = fast_exp2(CE * (M0 - nM0));
        float corr1 = fast_exp2(CE * (M1 - nM1));

        uint32_t pa[8][4];
        float s0 = 0.f, s1 = 0.f;
        #pragma unroll
        for (int k2 = 0; k2 < 8; k2++) {
            float p00 = fast_exp2(CE * (sf[2*k2][0]   - nM0));
            float p01 = fast_exp2(CE * (sf[2*k2][1]   - nM0));
            float p02 = fast_exp2(CE * (sf[2*k2][2]   - nM1));
            float p03 = fast_exp2(CE * (sf[2*k2][3]   - nM1));
            float p10 = fast_exp2(CE * (sf[2*k2+1][0] - nM0));
            float p11 = fast_exp2(CE * (sf[2*k2+1][1] - nM0));
            float p12 = fast_exp2(CE * (sf[2*k2+1][2] - nM1));
            float p13 = fast_exp2(CE * (sf[2*k2+1][3] - nM1));
            s0 += p00 + p01 + p10 + p11;
            s1 += p02 + p03 + p12 + p13;
            pa[k2][0] = pack_h2(p00, p01);
            pa[k2][1] = pack_h2(p02, p03);
            pa[k2][2] = pack_h2(p10, p11);
            pa[k2][3] = pack_h2(p12, p13);
        }
        s0 += __shfl_xor_sync(0xffffffffu, s0, 1);
        s0 += __shfl_xor_sync(0xffffffffu, s0, 2);
        s1 += __shfl_xor_sync(0xffffffffu, s1, 1);
        s1 += __shfl_xor_sync(0xffffffffu, s1, 2);
        L0 = L0 * corr0 + s0;
        L1 = L1 * corr1 + s1;
        M0 = nM0; M1 = nM1;

        #pragma unroll
        for (int j = 0; j < 8; j++) {
            of[j][0] *= corr0; of[j][1] *= corr0;
            of[j][2] *= corr1; of[j][3] *= corr1;
        }

        #pragma unroll
        for (int k2 = 0; k2 < 8; k2++) {
            #pragma unroll
            for (int jp = 0; jp < 4; jp++) {
                uint32_t r0, r1, r2, r3;
                LDSM_X4_T(r0, r1, r2, r3,
                          vb + (row_lds[k2] ^ (uint32_t)(jp * 32)));
                mma_f16(of[jp * 2],     pa[k2][0], pa[k2][1], pa[k2][2], pa[k2][3], r0, r1);
                mma_f16(of[jp * 2 + 1], pa[k2][0], pa[k2][1], pa[k2][2], pa[k2][3], r2, r3);
            }
        }
    }

    float i0 = 1.0f / L0, i1 = 1.0f / L1;
    __half* Og = g_att_h + ((long long)(b * N_ + q0 + w * 16)) * D_ + h * HD_;
    #pragma unroll
    for (int j = 0; j < 8; j++) {
        *reinterpret_cast<__half2*>(&Og[(long long)gid * D_ + j * 8 + tig * 2]) =
            __floats2half2_rn(of[j][0] * i0, of[j][1] * i0);
        *reinterpret_cast<__half2*>(&Og[(long long)(gid + 8) * D_ + j * 8 + tig * 2]) =
            __floats2half2_rn(of[j][2] * i1, of[j][3] * i1);
    }
}

// ---------------- small kernels ----------------
__global__ void f2h_all_kernel(const float* s0, const float* s1, const float* s2,
                               const float* s3, const float* s4, const float* s5,
                               __half* d0, __half* d1, __half* d2,
                               __half* d3, __half* d4, __half* d5,
                               long long c1, long long c2, long long c3,
                               long long c4, long long c5, long long c6) {
    long long i = (long long)blockIdx.x * blockDim.x + threadIdx.x;
    if (blockIdx.x == 0) {
        if (threadIdx.x < E_) {
            g_cnt[threadIdx.x]  = 0;
            g_psum[threadIdx.x] = 0.0f;
            g_ctr[threadIdx.x]  = 0;
        }
        if (threadIdx.x == E_) g_done = 0;
    }
    if (i >= c6) return;
    const float* s; __half* d; long long base;
    if      (i < c1) { s = s0; d = d0; base = 0;  }
    else if (i < c2) { s = s1; d = d1; base = c1; }
    else if (i < c3) { s = s2; d = d2; base = c2; }
    else if (i < c4) { s = s3; d = d3; base = c3; }
    else if (i < c5) { s = s4; d = d4; base = c4; }
    else             { s = s5; d = d5; base = c5; }
    long long j = i - base;
    const float4* s4p = reinterpret_cast<const float4*>(s);
    float4 a = s4p[j * 2], bb = s4p[j * 2 + 1];
    union { __half2 h[4]; uint4 u; } pack;
    pack.h[0] = __floats2half2_rn(a.x, a.y);
    pack.h[1] = __floats2half2_rn(a.z, a.w);
    pack.h[2] = __floats2half2_rn(bb.x, bb.y);
    pack.h[3] = __floats2half2_rn(bb.z, bb.w);
    reinterpret_cast<uint4*>(d)[j] = pack.u;
}

// Router: warp per token. Inline LN + xn_h store, logits, softmax, top-2,
// counts + psum atomics. Last block finalizes scan + lb (ticket).
__global__ void router_kernel(const float* __restrict__ x, const float* __restrict__ Wr,
                              const float* __restrict__ g, const float* __restrict__ bb,
                              float* __restrict__ out, int out_size) {
    int warp = (blockIdx.x * blockDim.x + threadIdx.x) >> 5;
    int lane = threadIdx.x & 31;
    if (warp < T_) {
        const float* xr = x + (long long)warp * D_;
        float xv[32];
        float s = 0.f;
        #pragma unroll
        for (int ii = 0; ii < 32; ii++) { xv[ii] = xr[lane + 32 * ii]; s += xv[ii]; }
        #pragma unroll
        for (int o = 16; o; o >>= 1) s += __shfl_xor_sync(0xffffffffu, s, o);
        float m = s * (1.0f / D_);
        float q = 0.f;
        #pragma unroll
        for (int ii = 0; ii < 32; ii++) { float d = xv[ii] - m; q += d * d; }
        #pragma unroll
        for (int o = 16; o; o >>= 1) q += __shfl_xor_sync(0xffffffffu, q, o);
        float rstd = rsqrtf(q * (1.0f / D_) + 1e-5f);

        float acc[E_];
        #pragma unroll
        for (int e = 0; e < E_; e++) acc[e] = 0.f;
        #pragma unroll
        for (int ii = 0; ii < 32; ii++) {
            int i = lane + 32 * ii;
            float xn = (xv[ii] - m) * rstd * g[i] + bb[i];
            g_xn_h[(long long)warp * D_ + i] = __float2half(xn);
            #pragma unroll
            for (int e = 0; e < E_; e++) acc[e] += xn * Wr[e * D_ + i];
        }
        #pragma unroll
        for (int e = 0; e < E_; e++)
            #pragma unroll
            for (int o = 16; o; o >>= 1) acc[e] += __shfl_xor_sync(0xffffffffu, acc[e], o);
        if (lane == 0) {
            float mx = acc[0];
            #pragma unroll
            for (int e = 1; e < E_; e++) mx = fmaxf(mx, acc[e]);
            float p[E_], ss = 0.f;
            #pragma unroll
            for (int e = 0; e < E_; e++) { p[e] = expf(acc[e] - mx); ss += p[e]; }
            float inv = 1.0f / ss;
            #pragma unroll
            for (int e = 0; e < E_; e++) {
                p[e] *= inv;
                atomicAdd(&g_psum[e], p[e]);
            }
            int i0 = 0;
            #pragma unroll
            for (int e = 1; e < E_; e++) if (p[e] > p[i0]) i0 = e;
            int i1 = (i0 == 0) ? 1 : 0;
            #pragma unroll
            for (int e = 0; e < E_; e++) if (e != i0 && p[e] > p[i1]) i1 = e;
            float v0 = p[i0], v1 = p[i1];
            float wsum = v0 + v1 + 1e-6f;
            g_topi[warp * 2 + 0] = i0;
            g_topi[warp * 2 + 1] = i1;
            g_topw[warp * 2 + 0] = v0 / wsum;
            g_topw[warp * 2 + 1] = v1 / wsum;
            atomicAdd(&g_cnt[i0], 1);
            atomicAdd(&g_cnt[i1], 1);
        }
    }
    __syncthreads();
    if (threadIdx.x == 0) {
        __threadfence();
        int t = atomicAdd(&g_done, 1);
        if (t == (int)gridDim.x - 1) {
            int cnt[E_];
            float ps[E_];
            #pragma unroll
            for (int e = 0; e < E_; e++) {
                cnt[e] = atomicAdd(&g_cnt[e], 0);
                ps[e]  = atomicAdd(&g_psum[e], 0.0f);
            }
            int s = 0;
            #pragma unroll
            for (int e = 0; e < E_; e++) { g_off[e] = s; s += cnt[e]; }
            g_off[E_] = s;
            float lb = 0.f;
            float denom = (float)A_ + 1e-6f;
            #pragma unroll
            for (int e = 0; e < E_; e++)
                lb += ((float)cnt[e] / denom) * ps[e];
            lb *= (float)E_;
            if (out_size > (int)TD) out[TD] = lb;
        }
    }
}

// grid-parallel scatter (global atomics on 12 counters)
__global__ void scatter_kernel() {
    int idx = blockIdx.x * blockDim.x + threadIdx.x;
    if (idx >= A_) return;
    int e = g_topi[idx];
    int pos = g_off[e] + atomicAdd(&g_ctr[e], 1);
    g_tok[pos]  = idx >> 1;
    g_aidx[idx] = pos;
}

// combine Q,K,V (half proj -> half q/k/v)
__global__ void combine_qkv_kernel() {
    long long t = blockIdx.x;
    int tid = threadIdx.x;
    int a0 = g_aidx[t * 2 + 0], a1 = g_aidx[t * 2 + 1];
    float w0 = g_topw[t * 2 + 0], w1 = g_topw[t * 2 + 1];
    const __half2* pQ = reinterpret_cast<const __half2*>(g_projQKV);
    const __half2* pK = reinterpret_cast<const __half2*>(g_projQKV + (long long)A_ * D_);
    const __half2* pV = reinterpret_cast<const __half2*>(g_projQKV + 2LL * A_ * D_);
    long long r0 = (long long)a0 * (D_ / 2), r1 = (long long)a1 * (D_ / 2);
    long long tb = t * (D_ / 2);
    #pragma unroll
    for (int i = 0; i < 2; i++) {
        int c = tid + 256 * i;
        float2 q0 = __half22float2(pQ[r0 + c]), q1 = __half22float2(pQ[r1 + c]);
        float2 k0 = __half22float2(pK[r0 + c]), k1 = __half22float2(pK[r1 + c]);
        float2 v0 = __half22float2(pV[r0 + c]), v1 = __half22float2(pV[r1 + c]);
        reinterpret_cast<__half2*>(g_q_h)[tb + c] =
            __floats2half2_rn(w0 * q0.x + w1 * q1.x, w0 * q0.y + w1 * q1.y);
        reinterpret_cast<__half2*>(g_k_h)[tb + c] =
            __floats2half2_rn(w0 * k0.x + w1 * k1.x, w0 * k0.y + w1 * k1.y);
        reinterpret_cast<__half2*>(g_v_h)[tb + c] =
            __floats2half2_rn(w0 * v0.x + w1 * v1.x, w0 * v0.y + w1 * v1.y);
    }
}

// LN2 fused with combine_o
__global__ void ln2_fused_kernel(const float* __restrict__ x,
                                 const float* __restrict__ g, const float* __restrict__ b) {
    __shared__ float sh[33];
    long long row = blockIdx.x;
    int tid = threadIdx.x;
    int a0 = g_aidx[row * 2 + 0], a1 = g_aidx[row * 2 + 1];
    float w0 = g_topw[row * 2 + 0], w1 = g_topw[row * 2 + 1];
    const __half* pO = g_projQKV;
    long long r0 = (long long)a0 * D_, r1 = (long long)a1 * D_;
    float v[4];
    #pragma unroll
    for (int i = 0; i < 4; i++) {
        int c = tid + 256 * i;
        float o = w0 * __half2float(pO[r0 + c]) + w1 * __half2float(pO[r1 + c]);
        v[i] = x[row * D_ + c] + o;
        g_h[row * D_ + c] = v[i];
    }
    float s = v[0] + v[1] + v[2] + v[3];
    #pragma unroll
    for (int o = 16; o; o >>= 1) s += __shfl_xor_sync(0xffffffffu, s, o);
    if ((tid & 31) == 0) sh[tid >> 5] = s;
    __syncthreads();
    if (tid < 32) {
        s = (tid < 8) ? sh[tid] : 0.0f;
        #pragma unroll
        for (int o = 16; o; o >>= 1) s += __shfl_xor_sync(0xffffffffu, s, o);
        if (tid == 0) sh[0] = s;
    }
    __syncthreads();
    float m = sh[0] * (1.0f / D_);
    __syncthreads();
    float q = 0.f;
    #pragma unroll
    for (int i = 0; i < 4; i++) { float d = v[i] - m; q += d * d; }
    #pragma unroll
    for (int o = 16; o; o >>= 1) q += __shfl_xor_sync(0xffffffffu, q, o);
    if ((tid & 31) == 0) sh[tid >> 5] = q;
    __syncthreads();
    if (tid < 32) {
        q = (tid < 8) ? sh[tid] : 0.0f;
        #pragma unroll
        for (int o = 16; o; o >>= 1) q += __shfl_xor_sync(0xffffffffu, q, o);
        if (tid == 0) sh[0] = q;
    }
    __syncthreads();
    float rstd = rsqrtf(sh[0] * (1.0f / D_) + 1e-5f);
    #pragma unroll
    for (int i = 0; i < 4; i++) {
        int c = tid + 256 * i;
        g_hn_h[row * D_ + c] = __float2half((v[i] - m) * rstd * g[c] + b[c]);
    }
}

// ---------------- host launch ----------------
extern "C" void kernel_launch(void* const* d_in, const int* in_sizes, int n_in,
                              void* d_out, int out_size) {
    const float* x   = (const float*)d_in[0];
    const float* Wr  = (const float*)d_in[1];
    const float* Wq  = (const float*)d_in[2];
    const float* Wk  = (const float*)d_in[3];
    const float* Wv  = (const float*)d_in[4];
    const float* Wo  = (const float*)d_in[5];
    const float* W1  = (const float*)d_in[6];
    const float* b1  = (const float*)d_in[7];
    const float* W2  = (const float*)d_in[8];
    const float* b2  = (const float*)d_in[9];
    const float* g1  = (const float*)d_in[10];
    const float* be1 = (const float*)d_in[11];
    const float* g2  = (const float*)d_in[12];
    const float* be2 = (const float*)d_in[13];
    float* out = (float*)d_out;

    float  *p_h;
    __half *p_xn_h, *p_att_h, *p_hn_h, *p_ff1_h, *p_projQKV;
    __half *p_Wqkv_h, *p_Wo_h, *p_W1_h, *p_W2_h;
    int *p_off, *p_tok;
    cudaGetSymbolAddress((void**)&p_xn_h,   g_xn_h);
    cudaGetSymbolAddress((void**)&p_projQKV,g_projQKV);
    cudaGetSymbolAddress((void**)&p_att_h,  g_att_h);
    cudaGetSymbolAddress((void**)&p_h,      g_h);
    cudaGetSymbolAddress((void**)&p_hn_h,   g_hn_h);
    cudaGetSymbolAddress((void**)&p_ff1_h,  g_ff1_h);
    cudaGetSymbolAddress((void**)&p_Wqkv_h, g_Wqkv_h);
    cudaGetSymbolAddress((void**)&p_Wo_h,   g_Wo_h);
    cudaGetSymbolAddress((void**)&p_W1_h,   g_W1_h);
    cudaGetSymbolAddress((void**)&p_W2_h,   g_W2_h);
    cudaGetSymbolAddress((void**)&p_off,    g_off);
    cudaGetSymbolAddress((void**)&p_tok,    g_tok);

    const long long EDD  = (long long)E_ * D_ * D_;
    const long long FFDD = (long long)FF_ * D_ * D_;
    const long long DD   = (long long)D_ * D_;
    cudaFuncSetAttribute(gemm_h,
                         cudaFuncAttributeMaxDynamicSharedMemorySize, GH_SMEM);
    cudaFuncSetAttribute(flash_attn_h,
                         cudaFuncAttributeMaxDynamicSharedMemorySize, FAH_SMEM);

    // fused weight conversion + counter init
    {
        long long n8e = EDD / 8, n8f = FFDD / 8;
        long long c1 = n8e, c2 = 2*n8e, c3 = 3*n8e, c4 = 4*n8e,
                  c5 = 4*n8e + n8f, c6 = 4*n8e + 2*n8f;
        int blocks = (int)((c6 + 255) / 256);
        f2h_all_kernel<<<blocks, 256>>>(Wq, Wk, Wv, Wo, W1, W2,
            p_Wqkv_h, p_Wqkv_h + EDD, p_Wqkv_h + 2*EDD, p_Wo_h, p_W1_h, p_W2_h,
            c1, c2, c3, c4, c5, c6);
    }

    router_kernel<<<T_ / 8, 256>>>(x, Wr, g1, be1, out, out_size);
    scatter_kernel<<<A_ / 256, 256>>>();

    // merged grouped QKV GEMM: z = p*E + e  (y=12: max expert load 1536 rows)
    gemm_h<<<dim3(D_ / 128, 12, 3 * E_), 256, GH_SMEM>>>(
        p_xn_h, p_Wqkv_h, nullptr, p_projQKV,
        D_, D_, D_, D_, E_, EDD, DD, (long long)A_ * D_,
        p_off, p_tok, A_, 0, nullptr, nullptr);
    combine_qkv_kernel<<<T_, 256>>>();

    flash_attn_h<<<dim3(N_ / 128, B_ * H_), 256, FAH_SMEM>>>();

    // grouped O projection (into proj slot 0); combine fused into LN2
    gemm_h<<<dim3(D_ / 128, 12, E_), 256, GH_SMEM>>>(
        p_att_h, p_Wo_h, nullptr, p_projQKV,
        D_, D_, D_, D_, E_, 0, DD, 0,
        p_off, p_tok, A_, 0, nullptr, nullptr);

    ln2_fused_kernel<<<T_, 256>>>(x, g2, be2);

    // FFN1
    gemm_h<<<dim3(FF_ * D_ / 128, T_ / 128, 1), 256, GH_SMEM>>>(
        p_hn_h, p_W1_h, nullptr, p_ff1_h,
        D_, D_, D_, FF_ * D_, 1, 0, 0, 0,
        nullptr, nullptr, T_, 2, b1, nullptr);

    // FFN2 -> d_out
    gemm_h<<<dim3(D_ / 128, T_ / 128, 1), 256, GH_SMEM>>>(
        p_ff1_h, p_W2_h, out, nullptr,
        FF_ * D_, FF_ * D_, FF_ * D_, D_, 1, 0, 0, 0,
        nullptr, nullptr, T_, 3, b2, p_h);
}